// round 6
// baseline (speedup 1.0000x reference)
#include <cuda_runtime.h>
#include <math.h>

#define HEADS 16
#define GROUPS 4
#define BATCH 2
#define SEQ 2048
#define DM 2048
#define DKV 512
#define HD 128
#define KD 2048

// Scratch (allocation-free rule: __device__ globals)
__device__ float g_q[BATCH * SEQ * DM];
__device__ float g_k[BATCH * SEQ * DKV];
__device__ float g_v[BATCH * SEQ * DKV];

// ---------------------------------------------------------------------------
// helpers
// ---------------------------------------------------------------------------
__device__ __forceinline__ unsigned f2tf(float f) {
    unsigned u;
    asm("cvt.rna.tf32.f32 %0, %1;" : "=r"(u) : "f"(f));
    return u;
}

__device__ __forceinline__ float fexp2(float x) {
    float r;
    asm("ex2.approx.f32 %0, %1;" : "=f"(r) : "f"(x));
    return r;
}

__device__ __forceinline__ void mma8(float c[4], const unsigned a[4],
                                     const unsigned b[2]) {
    asm volatile(
        "mma.sync.aligned.m16n8k8.row.col.f32.tf32.tf32.f32 "
        "{%0,%1,%2,%3}, {%4,%5,%6,%7}, {%8,%9}, {%0,%1,%2,%3};\n"
        : "+f"(c[0]), "+f"(c[1]), "+f"(c[2]), "+f"(c[3])
        : "r"(a[0]), "r"(a[1]), "r"(a[2]), "r"(a[3]), "r"(b[0]), "r"(b[1]));
}

__device__ __forceinline__ void ldmx4(unsigned r[4], const float* p) {
    unsigned addr = (unsigned)__cvta_generic_to_shared(p);
    asm volatile(
        "ldmatrix.sync.aligned.m8n8.x4.shared.b16 {%0,%1,%2,%3}, [%4];"
        : "=r"(r[0]), "=r"(r[1]), "=r"(r[2]), "=r"(r[3])
        : "r"(addr));
}

// ---------------------------------------------------------------------------
// Fused QKV projection GEMM, 512 threads (16 warps), 2-stage pipeline.
// CTA tile 128(m) x 256(n) x 32(k); warp tile 64x32 (2m x 8n warp grid).
// ---------------------------------------------------------------------------
#define GLDA 36
#define GSTAGE (128 * GLDA + 256 * GLDA)
#define GEMM_SMEM_FLOATS (2 * GSTAGE)

__global__ __launch_bounds__(512, 1) void gemm_qkv(const float* __restrict__ x,
                                                   const float* __restrict__ Wq,
                                                   const float* __restrict__ Wk,
                                                   const float* __restrict__ Wv) {
    extern __shared__ float gsm[];

    const int tid = threadIdx.x;
    const int w = tid >> 5;
    const int lane = tid & 31;
    const int lg = lane >> 2;
    const int t4 = lane & 3;
    const int wm = (w & 1) * 64;
    const int wn = (w >> 1) * 32;
    const int mBase = blockIdx.y * 128;
    const int nb = blockIdx.x;

    const float* W;
    float* C;
    int cN, nl0;
    if (nb < 8)       { W = Wq; C = g_q; cN = DM;  nl0 = nb * 256; }
    else if (nb < 10) { W = Wk; C = g_k; cN = DKV; nl0 = (nb - 8) * 256; }
    else              { W = Wv; C = g_v; cN = DKV; nl0 = (nb - 10) * 256; }

    float acc[4][4][4];
#pragma unroll
    for (int mt = 0; mt < 4; mt++)
#pragma unroll
        for (int nt = 0; nt < 4; nt++)
#pragma unroll
            for (int i = 0; i < 4; i++) acc[mt][nt][i] = 0.f;

    const int grow = tid >> 3;        // 0..63
    const int gcol = (tid & 7) * 4;   // 0..28

    const float* ap = x + (size_t)(mBase + grow) * KD + gcol;
    const float* wp = W + (size_t)(nl0 + grow) * KD + gcol;

    const int aRow = wm + ((lane >> 3) & 1) * 8 + (lane & 7);
    const int aCol = (lane >> 4) * 4;
    const int bRow = wn + ((lane >> 4) & 1) * 8 + (lane & 7);
    const int bCol = ((lane >> 3) & 1) * 4;

    float4 pa[2], pb[4];
    const int ktiles = KD / 32;

    // prologue: tile0 -> stage0, prefetch tile1
#pragma unroll
    for (int p = 0; p < 2; p++) pa[p] = *(const float4*)(ap + (size_t)p * 64 * KD);
#pragma unroll
    for (int p = 0; p < 4; p++) pb[p] = *(const float4*)(wp + (size_t)p * 64 * KD);
    {
        float* As = gsm;
        float* Bs = gsm + 128 * GLDA;
#pragma unroll
        for (int p = 0; p < 2; p++) {
            float4 va = pa[p];
            *(float4*)&As[(p * 64 + grow) * GLDA + gcol] =
                make_float4(__uint_as_float(f2tf(va.x)), __uint_as_float(f2tf(va.y)),
                            __uint_as_float(f2tf(va.z)), __uint_as_float(f2tf(va.w)));
        }
#pragma unroll
        for (int p = 0; p < 4; p++) {
            float4 vb = pb[p];
            *(float4*)&Bs[(p * 64 + grow) * GLDA + gcol] =
                make_float4(__uint_as_float(f2tf(vb.x)), __uint_as_float(f2tf(vb.y)),
                            __uint_as_float(f2tf(vb.z)), __uint_as_float(f2tf(vb.w)));
        }
    }
#pragma unroll
    for (int p = 0; p < 2; p++)
        pa[p] = *(const float4*)(ap + 32 + (size_t)p * 64 * KD);
#pragma unroll
    for (int p = 0; p < 4; p++)
        pb[p] = *(const float4*)(wp + 32 + (size_t)p * 64 * KD);
    __syncthreads();

    for (int kt = 0; kt < ktiles; kt++) {
        const float* As = gsm + (kt & 1) * GSTAGE;
        const float* Bs = As + 128 * GLDA;

#pragma unroll
        for (int ks = 0; ks < 4; ks++) {
            const int k0 = ks * 8;
            unsigned af[4][4], bf[2][4];
#pragma unroll
            for (int mt = 0; mt < 4; mt++)
                ldmx4(af[mt], &As[(aRow + mt * 16) * GLDA + k0 + aCol]);
#pragma unroll
            for (int ntp = 0; ntp < 2; ntp++)
                ldmx4(bf[ntp], &Bs[(bRow + ntp * 16) * GLDA + k0 + bCol]);
#pragma unroll
            for (int mt = 0; mt < 4; mt++)
#pragma unroll
                for (int nt = 0; nt < 4; nt++)
                    mma8(acc[mt][nt], af[mt], &bf[nt >> 1][(nt & 1) * 2]);
        }

        if (kt + 1 < ktiles) {
            float* An = gsm + ((kt + 1) & 1) * GSTAGE;
            float* Bn = An + 128 * GLDA;
#pragma unroll
            for (int p = 0; p < 2; p++) {
                float4 va = pa[p];
                *(float4*)&An[(p * 64 + grow) * GLDA + gcol] =
                    make_float4(__uint_as_float(f2tf(va.x)), __uint_as_float(f2tf(va.y)),
                                __uint_as_float(f2tf(va.z)), __uint_as_float(f2tf(va.w)));
            }
#pragma unroll
            for (int p = 0; p < 4; p++) {
                float4 vb = pb[p];
                *(float4*)&Bn[(p * 64 + grow) * GLDA + gcol] =
                    make_float4(__uint_as_float(f2tf(vb.x)), __uint_as_float(f2tf(vb.y)),
                                __uint_as_float(f2tf(vb.z)), __uint_as_float(f2tf(vb.w)));
            }
        }
        if (kt + 2 < ktiles) {
            const float* an = ap + (kt + 2) * 32;
            const float* wn2 = wp + (kt + 2) * 32;
#pragma unroll
            for (int p = 0; p < 2; p++)
                pa[p] = *(const float4*)(an + (size_t)p * 64 * KD);
#pragma unroll
            for (int p = 0; p < 4; p++)
                pb[p] = *(const float4*)(wn2 + (size_t)p * 64 * KD);
        }
        __syncthreads();
    }

#pragma unroll
    for (int mt = 0; mt < 4; mt++)
#pragma unroll
        for (int nt = 0; nt < 4; nt++) {
            const int row = mBase + wm + mt * 16 + lg;
            const int col = nl0 + wn + nt * 8 + 2 * t4;
            *(float2*)&C[(size_t)row * cN + col] =
                make_float2(acc[mt][nt][0], acc[mt][nt][1]);
            *(float2*)&C[(size_t)(row + 8) * cN + col] =
                make_float2(acc[mt][nt][2], acc[mt][nt][3]);
        }
}

// ---------------------------------------------------------------------------
// Flash attention, d-split warp layout for 2 CTAs/SM.
// BQ=64, BK=64, 8 warps: warp w -> q-rows (w&3)*16, d-half (w>>2)*64.
// Phase A duplicated across warp pairs; oacc/sacc = 32 regs each.
// ---------------------------------------------------------------------------
#define BQ 64
#define BK 64
#define LDK 132
#define LDV 136
#define LDQS 132
#define ATTN_SMEM_FLOATS (BQ * LDQS + BK * LDK + BK * LDV)  // 25600 = 100KB

__global__ __launch_bounds__(256, 2) void attn_mma(const float* __restrict__ q,
                                                   const float* __restrict__ k,
                                                   const float* __restrict__ v,
                                                   float* __restrict__ out) {
    extern __shared__ float sm[];
    float* Qstage = sm;                  // [BQ][LDQS], persistent
    float* Ks = sm + BQ * LDQS;          // [BK][LDK]
    float* Vs = Ks + BK * LDK;           // [BK][LDV]

    const int tid = threadIdx.x;
    const int w = tid >> 5;
    const int lane = tid & 31;
    const int lg = lane >> 2;
    const int t4 = lane & 3;

    const int qt = gridDim.x - 1 - blockIdx.x;   // heavy tiles first
    const int h = blockIdx.y;
    const int b = blockIdx.z;
    const int grp = h / (HEADS / GROUPS);
    const int qBase = qt * BQ;
    const int qrow0 = (w & 3) * 16;
    const int dhalf = (w >> 2) * 64;

    const float qscale = 0.08838834764831845f * 1.4426950408889634f;

    const int nkt = qt + 1;
    const int ldrow = tid >> 5;          // 0..7
    const size_t kvcol = grp * HD + lane * 4;

    // ---- stage Q (scaled + tf32) ----
#pragma unroll
    for (int rnd = 0; rnd < 8; rnd++) {
        const int row = ldrow + rnd * 8;
        const float* qp = q + (size_t)(b * SEQ + qBase + row) * DM + h * HD +
                          lane * 4;
        float4 val = *(const float4*)qp;
        *(float4*)&Qstage[row * LDQS + lane * 4] =
            make_float4(__uint_as_float(f2tf(val.x * qscale)),
                        __uint_as_float(f2tf(val.y * qscale)),
                        __uint_as_float(f2tf(val.z * qscale)),
                        __uint_as_float(f2tf(val.w * qscale)));
    }
    // ---- K/V tile 0 ----
#pragma unroll
    for (int rnd = 0; rnd < 8; rnd++) {
        const int row = ldrow + rnd * 8;
        const size_t base = (size_t)(b * SEQ + row) * DKV + kvcol;
        float4 kv4 = *(const float4*)(k + base);
        *(float4*)&Ks[row * LDK + lane * 4] =
            make_float4(__uint_as_float(f2tf(kv4.x)), __uint_as_float(f2tf(kv4.y)),
                        __uint_as_float(f2tf(kv4.z)), __uint_as_float(f2tf(kv4.w)));
        float4 vv4 = *(const float4*)(v + base);
        *(float4*)&Vs[row * LDV + lane * 4] =
            make_float4(__uint_as_float(f2tf(vv4.x)), __uint_as_float(f2tf(vv4.y)),
                        __uint_as_float(f2tf(vv4.z)), __uint_as_float(f2tf(vv4.w)));
    }
    __syncthreads();

    float oacc[8][4];
#pragma unroll
    for (int nt = 0; nt < 8; nt++)
#pragma unroll
        for (int i = 0; i < 4; i++) oacc[nt][i] = 0.f;

    float m0 = -1e30f, m1 = -1e30f, l0 = 0.f, l1 = 0.f;
    const int row0g = qBase + qrow0 + lg;

    const int kRow = ((lane >> 4) & 1) * 8 + (lane & 7);
    const int kCol = ((lane >> 3) & 1) * 4;
    const int qRow = qrow0 + ((lane >> 3) & 1) * 8 + (lane & 7);
    const int qCol = (lane >> 4) * 4;

    for (int kt = 0; kt < nkt; kt++) {
        const int kBase = kt * BK;

        // ---- phase A: S = Q K^T (16 rows x 64 cols per warp) ----
        float sacc[8][4];
#pragma unroll
        for (int nt = 0; nt < 8; nt++)
#pragma unroll
            for (int i = 0; i < 4; i++) sacc[nt][i] = 0.f;

#pragma unroll
        for (int ks = 0; ks < 16; ks++) {
            const int k0 = ks * 8;
            unsigned qf[4];
            ldmx4(qf, &Qstage[qRow * LDQS + k0 + qCol]);
#pragma unroll
            for (int ntp = 0; ntp < 4; ntp++) {
                unsigned bq[4];
                ldmx4(bq, &Ks[(ntp * 16 + kRow) * LDK + k0 + kCol]);
                mma8(sacc[2 * ntp], qf, bq);
                mma8(sacc[2 * ntp + 1], qf, bq + 2);
            }
        }

        // ---- causal mask ----
        if (kBase + BK - 1 > qBase + qrow0) {
#pragma unroll
            for (int nt = 0; nt < 8; nt++) {
                const int c0 = kBase + nt * 8 + 2 * t4;
                if (c0 > row0g) sacc[nt][0] = -1e30f;
                if (c0 + 1 > row0g) sacc[nt][1] = -1e30f;
                if (c0 > row0g + 8) sacc[nt][2] = -1e30f;
                if (c0 + 1 > row0g + 8) sacc[nt][3] = -1e30f;
            }
        }

        // ---- online softmax (base-2), registers + quad shfl ----
        float mx0 = -1e30f, mx1 = -1e30f;
#pragma unroll
        for (int nt = 0; nt < 8; nt++) {
            mx0 = fmaxf(mx0, fmaxf(sacc[nt][0], sacc[nt][1]));
            mx1 = fmaxf(mx1, fmaxf(sacc[nt][2], sacc[nt][3]));
        }
        mx0 = fmaxf(mx0, __shfl_xor_sync(0xffffffff, mx0, 1));
        mx0 = fmaxf(mx0, __shfl_xor_sync(0xffffffff, mx0, 2));
        mx1 = fmaxf(mx1, __shfl_xor_sync(0xffffffff, mx1, 1));
        mx1 = fmaxf(mx1, __shfl_xor_sync(0xffffffff, mx1, 2));

        const float mn0 = fmaxf(m0, mx0);
        const float mn1 = fmaxf(m1, mx1);
        const float sc0 = fexp2(m0 - mn0);
        const float sc1 = fexp2(m1 - mn1);

        float sum0 = 0.f, sum1 = 0.f;
#pragma unroll
        for (int nt = 0; nt < 8; nt++) {
            float p0 = fexp2(sacc[nt][0] - mn0);
            float p1 = fexp2(sacc[nt][1] - mn0);
            float p2 = fexp2(sacc[nt][2] - mn1);
            float p3 = fexp2(sacc[nt][3] - mn1);
            sacc[nt][0] = p0; sacc[nt][1] = p1;
            sacc[nt][2] = p2; sacc[nt][3] = p3;
            sum0 += p0 + p1;
            sum1 += p2 + p3;
        }
        sum0 += __shfl_xor_sync(0xffffffff, sum0, 1);
        sum0 += __shfl_xor_sync(0xffffffff, sum0, 2);
        sum1 += __shfl_xor_sync(0xffffffff, sum1, 1);
        sum1 += __shfl_xor_sync(0xffffffff, sum1, 2);

        l0 = l0 * sc0 + sum0;  m0 = mn0;
        l1 = l1 * sc1 + sum1;  m1 = mn1;

#pragma unroll
        for (int nt = 0; nt < 8; nt++) {
            oacc[nt][0] *= sc0;
            oacc[nt][1] *= sc0;
            oacc[nt][2] *= sc1;
            oacc[nt][3] *= sc1;
        }

        // ---- phase C: O += P V over my d-half ----
        const int srcA = (lane & 28) | (t4 >> 1);
        const int srcB = srcA + 2;
        const bool odd = (t4 & 1);
#pragma unroll
        for (int ks = 0; ks < 8; ks++) {
            const float v0 = sacc[ks][0], v1 = sacc[ks][1];
            const float v2 = sacc[ks][2], v3 = sacc[ks][3];
            float x0 = __shfl_sync(0xffffffff, v0, srcA);
            float x1 = __shfl_sync(0xffffffff, v1, srcA);
            float y0 = __shfl_sync(0xffffffff, v0, srcB);
            float y1 = __shfl_sync(0xffffffff, v1, srcB);
            float z0 = __shfl_sync(0xffffffff, v2, srcA);
            float z1 = __shfl_sync(0xffffffff, v3, srcA);
            float u0 = __shfl_sync(0xffffffff, v2, srcB);
            float u1 = __shfl_sync(0xffffffff, v3, srcB);
            unsigned pf[4];
            pf[0] = f2tf(odd ? x1 : x0);
            pf[1] = f2tf(odd ? z1 : z0);
            pf[2] = f2tf(odd ? y1 : y0);
            pf[3] = f2tf(odd ? u1 : u0);

            const int k0 = ks * 8;
#pragma unroll
            for (int nt = 0; nt < 8; nt++) {
                unsigned bf[2];
                bf[0] = __float_as_uint(Vs[(k0 + t4) * LDV + dhalf + nt * 8 + lg]);
                bf[1] = __float_as_uint(Vs[(k0 + t4 + 4) * LDV + dhalf + nt * 8 + lg]);
                mma8(oacc[nt], pf, bf);
            }
        }

        // ---- load next K/V tile (single buffer) ----
        if (kt + 1 < nkt) {
            __syncthreads();
            const int kb = (kt + 1) * BK;
#pragma unroll
            for (int rnd = 0; rnd < 8; rnd++) {
                const int row = ldrow + rnd * 8;
                const size_t base = (size_t)(b * SEQ + kb + row) * DKV + kvcol;
                float4 kv4 = *(const float4*)(k + base);
                *(float4*)&Ks[row * LDK + lane * 4] =
                    make_float4(__uint_as_float(f2tf(kv4.x)), __uint_as_float(f2tf(kv4.y)),
                                __uint_as_float(f2tf(kv4.z)), __uint_as_float(f2tf(kv4.w)));
                float4 vv4 = *(const float4*)(v + base);
                *(float4*)&Vs[row * LDV + lane * 4] =
                    make_float4(__uint_as_float(f2tf(vv4.x)), __uint_as_float(f2tf(vv4.y)),
                                __uint_as_float(f2tf(vv4.z)), __uint_as_float(f2tf(vv4.w)));
            }
            __syncthreads();
        }
    }

    // ---- finalize + write (rows qrow0..+15, cols dhalf..+63) ----
    const float inv0 = 1.0f / l0;
    const float inv1 = 1.0f / l1;
#pragma unroll
    for (int nt = 0; nt < 8; nt++) {
        const int d = h * HD + dhalf + nt * 8 + 2 * t4;
        *(float2*)&out[(size_t)(b * SEQ + row0g) * DM + d] =
            make_float2(oacc[nt][0] * inv0, oacc[nt][1] * inv0);
        *(float2*)&out[(size_t)(b * SEQ + row0g + 8) * DM + d] =
            make_float2(oacc[nt][2] * inv1, oacc[nt][3] * inv1);
    }
}

// ---------------------------------------------------------------------------
extern "C" void kernel_launch(void* const* d_in, const int* in_sizes, int n_in,
                              void* d_out, int out_size) {
    const float* x = (const float*)d_in[0];
    const float* Wq = (const float*)d_in[1];
    const float* Wk = (const float*)d_in[2];
    const float* Wv = (const float*)d_in[3];
    float* out = (float*)d_out;

    float *pq = nullptr, *pk = nullptr, *pv = nullptr;
    cudaGetSymbolAddress((void**)&pq, g_q);
    cudaGetSymbolAddress((void**)&pk, g_k);
    cudaGetSymbolAddress((void**)&pv, g_v);

    static const size_t gemmSmem = GEMM_SMEM_FLOATS * sizeof(float);
    cudaFuncSetAttribute(gemm_qkv, cudaFuncAttributeMaxDynamicSharedMemorySize,
                         (int)gemmSmem);
    dim3 gthr(512);
    dim3 gg(12, 32);
    gemm_qkv<<<gg, gthr, gemmSmem>>>(x, Wq, Wk, Wv);

    static const size_t attnSmem = ATTN_SMEM_FLOATS * sizeof(float);
    cudaFuncSetAttribute(attn_mma, cudaFuncAttributeMaxDynamicSharedMemorySize,
                         (int)attnSmem);
    dim3 athr(256);
    dim3 ga(SEQ / BQ, HEADS, BATCH);
    attn_mma<<<ga, athr, attnSmem>>>(pq, pk, pv, out);
}

// round 7
// speedup vs baseline: 1.2490x; 1.2490x over previous
#include <cuda_runtime.h>
#include <math.h>

#define HEADS 16
#define GROUPS 4
#define BATCH 2
#define SEQ 2048
#define DM 2048
#define DKV 512
#define HD 128
#define KD 2048

// Scratch (allocation-free rule: __device__ globals)
__device__ float g_q[BATCH * SEQ * DM];
__device__ float g_k[BATCH * SEQ * DKV];
__device__ float g_v[BATCH * SEQ * DKV];

// ---------------------------------------------------------------------------
// helpers
// ---------------------------------------------------------------------------
__device__ __forceinline__ unsigned f2tf(float f) {
    unsigned u;
    asm("cvt.rna.tf32.f32 %0, %1;" : "=r"(u) : "f"(f));
    return u;
}

__device__ __forceinline__ float fexp2(float x) {
    float r;
    asm("ex2.approx.f32 %0, %1;" : "=f"(r) : "f"(x));
    return r;
}

__device__ __forceinline__ void mma8(float c[4], const unsigned a[4],
                                     const unsigned b[2]) {
    asm volatile(
        "mma.sync.aligned.m16n8k8.row.col.f32.tf32.tf32.f32 "
        "{%0,%1,%2,%3}, {%4,%5,%6,%7}, {%8,%9}, {%0,%1,%2,%3};\n"
        : "+f"(c[0]), "+f"(c[1]), "+f"(c[2]), "+f"(c[3])
        : "r"(a[0]), "r"(a[1]), "r"(a[2]), "r"(a[3]), "r"(b[0]), "r"(b[1]));
}

__device__ __forceinline__ void ldmx4(unsigned r[4], const float* p) {
    unsigned addr = (unsigned)__cvta_generic_to_shared(p);
    asm volatile(
        "ldmatrix.sync.aligned.m8n8.x4.shared.b16 {%0,%1,%2,%3}, [%4];"
        : "=r"(r[0]), "=r"(r[1]), "=r"(r[2]), "=r"(r[3])
        : "r"(addr));
}

// ---------------------------------------------------------------------------
// Fused QKV projection GEMM, 512 threads (16 warps), 2-stage pipeline.
// CTA tile 128(m) x 256(n) x 32(k); warp tile 64x32 (2m x 8n warp grid).
// (Round-6 version: measured ~292 us.)
// ---------------------------------------------------------------------------
#define GLDA 36
#define GSTAGE (128 * GLDA + 256 * GLDA)
#define GEMM_SMEM_FLOATS (2 * GSTAGE)

__global__ __launch_bounds__(512, 1) void gemm_qkv(const float* __restrict__ x,
                                                   const float* __restrict__ Wq,
                                                   const float* __restrict__ Wk,
                                                   const float* __restrict__ Wv) {
    extern __shared__ float gsm[];

    const int tid = threadIdx.x;
    const int w = tid >> 5;
    const int lane = tid & 31;
    const int lg = lane >> 2;
    const int t4 = lane & 3;
    const int wm = (w & 1) * 64;
    const int wn = (w >> 1) * 32;
    const int mBase = blockIdx.y * 128;
    const int nb = blockIdx.x;

    const float* W;
    float* C;
    int cN, nl0;
    if (nb < 8)       { W = Wq; C = g_q; cN = DM;  nl0 = nb * 256; }
    else if (nb < 10) { W = Wk; C = g_k; cN = DKV; nl0 = (nb - 8) * 256; }
    else              { W = Wv; C = g_v; cN = DKV; nl0 = (nb - 10) * 256; }

    float acc[4][4][4];
#pragma unroll
    for (int mt = 0; mt < 4; mt++)
#pragma unroll
        for (int nt = 0; nt < 4; nt++)
#pragma unroll
            for (int i = 0; i < 4; i++) acc[mt][nt][i] = 0.f;

    const int grow = tid >> 3;        // 0..63
    const int gcol = (tid & 7) * 4;   // 0..28

    const float* ap = x + (size_t)(mBase + grow) * KD + gcol;
    const float* wp = W + (size_t)(nl0 + grow) * KD + gcol;

    const int aRow = wm + ((lane >> 3) & 1) * 8 + (lane & 7);
    const int aCol = (lane >> 4) * 4;
    const int bRow = wn + ((lane >> 4) & 1) * 8 + (lane & 7);
    const int bCol = ((lane >> 3) & 1) * 4;

    float4 pa[2], pb[4];
    const int ktiles = KD / 32;

    // prologue: tile0 -> stage0, prefetch tile1
#pragma unroll
    for (int p = 0; p < 2; p++) pa[p] = *(const float4*)(ap + (size_t)p * 64 * KD);
#pragma unroll
    for (int p = 0; p < 4; p++) pb[p] = *(const float4*)(wp + (size_t)p * 64 * KD);
    {
        float* As = gsm;
        float* Bs = gsm + 128 * GLDA;
#pragma unroll
        for (int p = 0; p < 2; p++) {
            float4 va = pa[p];
            *(float4*)&As[(p * 64 + grow) * GLDA + gcol] =
                make_float4(__uint_as_float(f2tf(va.x)), __uint_as_float(f2tf(va.y)),
                            __uint_as_float(f2tf(va.z)), __uint_as_float(f2tf(va.w)));
        }
#pragma unroll
        for (int p = 0; p < 4; p++) {
            float4 vb = pb[p];
            *(float4*)&Bs[(p * 64 + grow) * GLDA + gcol] =
                make_float4(__uint_as_float(f2tf(vb.x)), __uint_as_float(f2tf(vb.y)),
                            __uint_as_float(f2tf(vb.z)), __uint_as_float(f2tf(vb.w)));
        }
    }
#pragma unroll
    for (int p = 0; p < 2; p++)
        pa[p] = *(const float4*)(ap + 32 + (size_t)p * 64 * KD);
#pragma unroll
    for (int p = 0; p < 4; p++)
        pb[p] = *(const float4*)(wp + 32 + (size_t)p * 64 * KD);
    __syncthreads();

    for (int kt = 0; kt < ktiles; kt++) {
        const float* As = gsm + (kt & 1) * GSTAGE;
        const float* Bs = As + 128 * GLDA;

#pragma unroll
        for (int ks = 0; ks < 4; ks++) {
            const int k0 = ks * 8;
            unsigned af[4][4], bf[2][4];
#pragma unroll
            for (int mt = 0; mt < 4; mt++)
                ldmx4(af[mt], &As[(aRow + mt * 16) * GLDA + k0 + aCol]);
#pragma unroll
            for (int ntp = 0; ntp < 2; ntp++)
                ldmx4(bf[ntp], &Bs[(bRow + ntp * 16) * GLDA + k0 + bCol]);
#pragma unroll
            for (int mt = 0; mt < 4; mt++)
#pragma unroll
                for (int nt = 0; nt < 4; nt++)
                    mma8(acc[mt][nt], af[mt], &bf[nt >> 1][(nt & 1) * 2]);
        }

        if (kt + 1 < ktiles) {
            float* An = gsm + ((kt + 1) & 1) * GSTAGE;
            float* Bn = An + 128 * GLDA;
#pragma unroll
            for (int p = 0; p < 2; p++) {
                float4 va = pa[p];
                *(float4*)&An[(p * 64 + grow) * GLDA + gcol] =
                    make_float4(__uint_as_float(f2tf(va.x)), __uint_as_float(f2tf(va.y)),
                                __uint_as_float(f2tf(va.z)), __uint_as_float(f2tf(va.w)));
            }
#pragma unroll
            for (int p = 0; p < 4; p++) {
                float4 vb = pb[p];
                *(float4*)&Bn[(p * 64 + grow) * GLDA + gcol] =
                    make_float4(__uint_as_float(f2tf(vb.x)), __uint_as_float(f2tf(vb.y)),
                                __uint_as_float(f2tf(vb.z)), __uint_as_float(f2tf(vb.w)));
            }
        }
        if (kt + 2 < ktiles) {
            const float* an = ap + (kt + 2) * 32;
            const float* wn2 = wp + (kt + 2) * 32;
#pragma unroll
            for (int p = 0; p < 2; p++)
                pa[p] = *(const float4*)(an + (size_t)p * 64 * KD);
#pragma unroll
            for (int p = 0; p < 4; p++)
                pb[p] = *(const float4*)(wn2 + (size_t)p * 64 * KD);
        }
        __syncthreads();
    }

#pragma unroll
    for (int mt = 0; mt < 4; mt++)
#pragma unroll
        for (int nt = 0; nt < 4; nt++) {
            const int row = mBase + wm + mt * 16 + lg;
            const int col = nl0 + wn + nt * 8 + 2 * t4;
            *(float2*)&C[(size_t)row * cN + col] =
                make_float2(acc[mt][nt][0], acc[mt][nt][1]);
            *(float2*)&C[(size_t)(row + 8) * cN + col] =
                make_float2(acc[mt][nt][2], acc[mt][nt][3]);
        }
}

// ---------------------------------------------------------------------------
// Register-resident flash attention (round-4 version: measured ~305 us).
// Br=128, Bc=64, 8 warps, single-buffered K/V, Q fragments in registers.
// ---------------------------------------------------------------------------
#define BQ 128
#define BK 64
#define LDK 132
#define LDV 136
#define LDQS 132
#define ATTN_SMEM_FLOATS (BK * LDK + BK * LDV)

__global__ __launch_bounds__(256, 1) void attn_mma(const float* __restrict__ q,
                                                   const float* __restrict__ k,
                                                   const float* __restrict__ v,
                                                   float* __restrict__ out) {
    extern __shared__ float sm[];
    float* Ks = sm;                 // [BK][LDK]
    float* Vs = sm + BK * LDK;      // [BK][LDV]
    float* Qstage = sm;             // [BQ][LDQS] overlay (pre-loop only)

    const int tid = threadIdx.x;
    const int w = tid >> 5;
    const int lane = tid & 31;
    const int lg = lane >> 2;
    const int t4 = lane & 3;

    const int qt = gridDim.x - 1 - blockIdx.x;   // heavy tiles first
    const int h = blockIdx.y;
    const int b = blockIdx.z;
    const int grp = h / (HEADS / GROUPS);
    const int qBase = qt * BQ;
    const int wq0 = w * 16;

    const float qscale = 0.08838834764831845f * 1.4426950408889634f;

    // ---- stage Q (scaled + tf32) then pull fragments to registers ----
#pragma unroll
    for (int rnd = 0; rnd < 16; rnd++) {
        const int row = (tid >> 5) + rnd * 8;
        const float* qp = q + (size_t)(b * SEQ + qBase + row) * DM + h * HD +
                          lane * 4;
        float4 val = *(const float4*)qp;
        *(float4*)&Qstage[row * LDQS + lane * 4] =
            make_float4(__uint_as_float(f2tf(val.x * qscale)),
                        __uint_as_float(f2tf(val.y * qscale)),
                        __uint_as_float(f2tf(val.z * qscale)),
                        __uint_as_float(f2tf(val.w * qscale)));
    }
    __syncthreads();

    unsigned qf[16][4];
    {
        const int qRow = wq0 + ((lane >> 3) & 1) * 8 + (lane & 7);
        const int qCol = (lane >> 4) * 4;
#pragma unroll
        for (int ks = 0; ks < 16; ks++)
            ldmx4(qf[ks], &Qstage[qRow * LDQS + ks * 8 + qCol]);
    }

    float oacc[16][4];
#pragma unroll
    for (int nt = 0; nt < 16; nt++)
#pragma unroll
        for (int i = 0; i < 4; i++) oacc[nt][i] = 0.f;

    float m0 = -1e30f, m1 = -1e30f, l0 = 0.f, l1 = 0.f;
    const int lastRow = qBase + wq0 + 15;
    const int row0g = qBase + wq0 + lg;
    const int nkt = (qBase + BQ) / BK;

    // phase-A ldmatrix address pieces
    const int kRow = ((lane >> 4) & 1) * 8 + (lane & 7);
    const int kCol = ((lane >> 3) & 1) * 4;

    for (int kt = 0; kt < nkt; kt++) {
        const int kBase = kt * BK;
        __syncthreads();

        // ---- cooperative K/V tile load (fp32 -> tf32 bits) ----
#pragma unroll
        for (int rnd = 0; rnd < 8; rnd++) {
            const int row = (tid >> 5) + rnd * 8;
            const size_t base = (size_t)(b * SEQ + kBase + row) * DKV +
                                grp * HD + lane * 4;
            float4 kv4 = *(const float4*)(k + base);
            *(float4*)&Ks[row * LDK + lane * 4] =
                make_float4(__uint_as_float(f2tf(kv4.x)), __uint_as_float(f2tf(kv4.y)),
                            __uint_as_float(f2tf(kv4.z)), __uint_as_float(f2tf(kv4.w)));
            float4 vv4 = *(const float4*)(v + base);
            *(float4*)&Vs[row * LDV + lane * 4] =
                make_float4(__uint_as_float(f2tf(vv4.x)), __uint_as_float(f2tf(vv4.y)),
                            __uint_as_float(f2tf(vv4.z)), __uint_as_float(f2tf(vv4.w)));
        }
        __syncthreads();

        if (kBase > lastRow) continue;   // warp-uniform; barrier counts match

        // ---- phase A: S = Q K^T (ldmatrix B-frags) ----
        float sacc[8][4];
#pragma unroll
        for (int nt = 0; nt < 8; nt++)
#pragma unroll
            for (int i = 0; i < 4; i++) sacc[nt][i] = 0.f;

#pragma unroll
        for (int ks = 0; ks < 16; ks++) {
            const int k0 = ks * 8;
#pragma unroll
            for (int ntp = 0; ntp < 4; ntp++) {
                unsigned bq[4];
                ldmx4(bq, &Ks[(ntp * 16 + kRow) * LDK + k0 + kCol]);
                mma8(sacc[2 * ntp], qf[ks], bq);
                mma8(sacc[2 * ntp + 1], qf[ks], bq + 2);
            }
        }

        // ---- causal mask ----
        if (kBase + BK - 1 > qBase + wq0) {
#pragma unroll
            for (int nt = 0; nt < 8; nt++) {
                const int c0 = kBase + nt * 8 + 2 * t4;
                if (c0 > row0g) sacc[nt][0] = -1e30f;
                if (c0 + 1 > row0g) sacc[nt][1] = -1e30f;
                if (c0 > row0g + 8) sacc[nt][2] = -1e30f;
                if (c0 + 1 > row0g + 8) sacc[nt][3] = -1e30f;
            }
        }

        // ---- online softmax (base-2), registers + quad shfl ----
        float mx0 = -1e30f, mx1 = -1e30f;
#pragma unroll
        for (int nt = 0; nt < 8; nt++) {
            mx0 = fmaxf(mx0, fmaxf(sacc[nt][0], sacc[nt][1]));
            mx1 = fmaxf(mx1, fmaxf(sacc[nt][2], sacc[nt][3]));
        }
        mx0 = fmaxf(mx0, __shfl_xor_sync(0xffffffff, mx0, 1));
        mx0 = fmaxf(mx0, __shfl_xor_sync(0xffffffff, mx0, 2));
        mx1 = fmaxf(mx1, __shfl_xor_sync(0xffffffff, mx1, 1));
        mx1 = fmaxf(mx1, __shfl_xor_sync(0xffffffff, mx1, 2));

        const float mn0 = fmaxf(m0, mx0);
        const float mn1 = fmaxf(m1, mx1);
        const float sc0 = fexp2(m0 - mn0);
        const float sc1 = fexp2(m1 - mn1);

        float sum0 = 0.f, sum1 = 0.f;
#pragma unroll
        for (int nt = 0; nt < 8; nt++) {
            float p0 = fexp2(sacc[nt][0] - mn0);
            float p1 = fexp2(sacc[nt][1] - mn0);
            float p2 = fexp2(sacc[nt][2] - mn1);
            float p3 = fexp2(sacc[nt][3] - mn1);
            sacc[nt][0] = p0; sacc[nt][1] = p1;
            sacc[nt][2] = p2; sacc[nt][3] = p3;
            sum0 += p0 + p1;
            sum1 += p2 + p3;
        }
        sum0 += __shfl_xor_sync(0xffffffff, sum0, 1);
        sum0 += __shfl_xor_sync(0xffffffff, sum0, 2);
        sum1 += __shfl_xor_sync(0xffffffff, sum1, 1);
        sum1 += __shfl_xor_sync(0xffffffff, sum1, 2);

        l0 = l0 * sc0 + sum0;  m0 = mn0;
        l1 = l1 * sc1 + sum1;  m1 = mn1;

#pragma unroll
        for (int nt = 0; nt < 16; nt++) {
            oacc[nt][0] *= sc0;
            oacc[nt][1] *= sc0;
            oacc[nt][2] *= sc1;
            oacc[nt][3] *= sc1;
        }

        // ---- phase C: O += P V ; P re-shaped C-frag -> A-frag via shfl ----
        const int srcA = (lane & 28) | (t4 >> 1);
        const int srcB = srcA + 2;
        const bool odd = (t4 & 1);
#pragma unroll
        for (int ks = 0; ks < 8; ks++) {
            const float v0 = sacc[ks][0], v1 = sacc[ks][1];
            const float v2 = sacc[ks][2], v3 = sacc[ks][3];
            float x0 = __shfl_sync(0xffffffff, v0, srcA);
            float x1 = __shfl_sync(0xffffffff, v1, srcA);
            float y0 = __shfl_sync(0xffffffff, v0, srcB);
            float y1 = __shfl_sync(0xffffffff, v1, srcB);
            float z0 = __shfl_sync(0xffffffff, v2, srcA);
            float z1 = __shfl_sync(0xffffffff, v3, srcA);
            float u0 = __shfl_sync(0xffffffff, v2, srcB);
            float u1 = __shfl_sync(0xffffffff, v3, srcB);
            unsigned pf[4];
            pf[0] = f2tf(odd ? x1 : x0);
            pf[1] = f2tf(odd ? z1 : z0);
            pf[2] = f2tf(odd ? y1 : y0);
            pf[3] = f2tf(odd ? u1 : u0);

            const int k0 = ks * 8;
#pragma unroll
            for (int nt = 0; nt < 16; nt++) {
                unsigned bf[2];
                bf[0] = __float_as_uint(Vs[(k0 + t4) * LDV + nt * 8 + lg]);
                bf[1] = __float_as_uint(Vs[(k0 + t4 + 4) * LDV + nt * 8 + lg]);
                mma8(oacc[nt], pf, bf);
            }
        }
    }

    // ---- finalize + write ----
    const float inv0 = 1.0f / l0;
    const float inv1 = 1.0f / l1;
#pragma unroll
    for (int nt = 0; nt < 16; nt++) {
        const int d = h * HD + nt * 8 + 2 * t4;
        *(float2*)&out[(size_t)(b * SEQ + row0g) * DM + d] =
            make_float2(oacc[nt][0] * inv0, oacc[nt][1] * inv0);
        *(float2*)&out[(size_t)(b * SEQ + row0g + 8) * DM + d] =
            make_float2(oacc[nt][2] * inv1, oacc[nt][3] * inv1);
    }
}

// ---------------------------------------------------------------------------
extern "C" void kernel_launch(void* const* d_in, const int* in_sizes, int n_in,
                              void* d_out, int out_size) {
    const float* x = (const float*)d_in[0];
    const float* Wq = (const float*)d_in[1];
    const float* Wk = (const float*)d_in[2];
    const float* Wv = (const float*)d_in[3];
    float* out = (float*)d_out;

    float *pq = nullptr, *pk = nullptr, *pv = nullptr;
    cudaGetSymbolAddress((void**)&pq, g_q);
    cudaGetSymbolAddress((void**)&pk, g_k);
    cudaGetSymbolAddress((void**)&pv, g_v);

    static const size_t gemmSmem = GEMM_SMEM_FLOATS * sizeof(float);
    cudaFuncSetAttribute(gemm_qkv, cudaFuncAttributeMaxDynamicSharedMemorySize,
                         (int)gemmSmem);
    dim3 gthr(512);
    dim3 gg(12, 32);
    gemm_qkv<<<gg, gthr, gemmSmem>>>(x, Wq, Wk, Wv);

    static const size_t attnSmem = ATTN_SMEM_FLOATS * sizeof(float);
    cudaFuncSetAttribute(attn_mma, cudaFuncAttributeMaxDynamicSharedMemorySize,
                         (int)attnSmem);
    dim3 athr(256);
    dim3 ga(SEQ / BQ, HEADS, BATCH);
    attn_mma<<<ga, athr, attnSmem>>>(pq, pk, pv, out);
}

// round 8
// speedup vs baseline: 1.6214x; 1.2982x over previous
#include <cuda_runtime.h>
#include <cuda_fp16.h>
#include <math.h>

#define HEADS 16
#define GROUPS 4
#define BATCH 2
#define SEQ 2048
#define DM 2048
#define DKV 512
#define HD 128
#define KD 2048

// Scratch (allocation-free rule: __device__ globals) — fp16 Q/K/V
__device__ __half g_q[BATCH * SEQ * DM];
__device__ __half g_k[BATCH * SEQ * DKV];
__device__ __half g_v[BATCH * SEQ * DKV];

// ---------------------------------------------------------------------------
// helpers
// ---------------------------------------------------------------------------
__device__ __forceinline__ float fexp2(float x) {
    float r;
    asm("ex2.approx.f32 %0, %1;" : "=f"(r) : "f"(x));
    return r;
}

__device__ __forceinline__ unsigned packh2(float lo, float hi) {
    __half2 h = __floats2half2_rn(lo, hi);
    return *reinterpret_cast<unsigned*>(&h);
}

__device__ __forceinline__ void mma16h(float c[4], const unsigned a[4],
                                       unsigned b0, unsigned b1) {
    asm volatile(
        "mma.sync.aligned.m16n8k16.row.col.f32.f16.f16.f32 "
        "{%0,%1,%2,%3}, {%4,%5,%6,%7}, {%8,%9}, {%0,%1,%2,%3};\n"
        : "+f"(c[0]), "+f"(c[1]), "+f"(c[2]), "+f"(c[3])
        : "r"(a[0]), "r"(a[1]), "r"(a[2]), "r"(a[3]), "r"(b0), "r"(b1));
}

__device__ __forceinline__ void ldmx4(unsigned r[4], const __half* p) {
    unsigned addr = (unsigned)__cvta_generic_to_shared(p);
    asm volatile(
        "ldmatrix.sync.aligned.m8n8.x4.shared.b16 {%0,%1,%2,%3}, [%4];"
        : "=r"(r[0]), "=r"(r[1]), "=r"(r[2]), "=r"(r[3])
        : "r"(addr));
}

__device__ __forceinline__ void ldmx4t(unsigned r[4], const __half* p) {
    unsigned addr = (unsigned)__cvta_generic_to_shared(p);
    asm volatile(
        "ldmatrix.sync.aligned.m8n8.x4.trans.shared.b16 {%0,%1,%2,%3}, [%4];"
        : "=r"(r[0]), "=r"(r[1]), "=r"(r[2]), "=r"(r[3])
        : "r"(addr));
}

// ---------------------------------------------------------------------------
// Fused QKV projection GEMM (fp16 operands, fp32 accum), 512 threads,
// 2-stage pipeline. CTA tile 128x256x32, warp tile 64x32.
// Epilogue stores fp16 (Q pre-scaled by 1/sqrt(hd)*log2e).
// ---------------------------------------------------------------------------
#define LDGH 40
#define GSTAGE_H (128 * LDGH + 256 * LDGH)          // halfs per stage
#define GEMM_SMEM_BYTES (2 * GSTAGE_H * 2)

__global__ __launch_bounds__(512, 1) void gemm_qkv(const float* __restrict__ x,
                                                   const float* __restrict__ Wq,
                                                   const float* __restrict__ Wk,
                                                   const float* __restrict__ Wv) {
    extern __shared__ __align__(16) char gsmRaw[];
    __half* gsm = (__half*)gsmRaw;

    const int tid = threadIdx.x;
    const int w = tid >> 5;
    const int lane = tid & 31;
    const int lg = lane >> 2;
    const int t4 = lane & 3;
    const int wm = (w & 1) * 64;
    const int wn = (w >> 1) * 32;
    const int mBase = blockIdx.y * 128;
    const int nb = blockIdx.x;

    const float qscale = 0.08838834764831845f * 1.4426950408889634f;

    const float* W;
    __half* C;
    int cN, nl0;
    float oscale;
    if (nb < 8)       { W = Wq; C = g_q; cN = DM;  nl0 = nb * 256;        oscale = qscale; }
    else if (nb < 10) { W = Wk; C = g_k; cN = DKV; nl0 = (nb - 8) * 256;  oscale = 1.f; }
    else              { W = Wv; C = g_v; cN = DKV; nl0 = (nb - 10) * 256; oscale = 1.f; }

    float acc[4][4][4];
#pragma unroll
    for (int mt = 0; mt < 4; mt++)
#pragma unroll
        for (int nt = 0; nt < 4; nt++)
#pragma unroll
            for (int i = 0; i < 4; i++) acc[mt][nt][i] = 0.f;

    const int grow = tid >> 3;        // 0..63
    const int gcol = (tid & 7) * 4;   // 0..28

    const float* ap = x + (size_t)(mBase + grow) * KD + gcol;
    const float* wp = W + (size_t)(nl0 + grow) * KD + gcol;

    const int lmRow = lane & 15;
    const int lmColH = (lane >> 4) * 8;

    float4 pa[2], pb[4];
    const int ktiles = KD / 32;

    // prologue: tile0 -> stage0, prefetch tile1
#pragma unroll
    for (int p = 0; p < 2; p++) pa[p] = *(const float4*)(ap + (size_t)p * 64 * KD);
#pragma unroll
    for (int p = 0; p < 4; p++) pb[p] = *(const float4*)(wp + (size_t)p * 64 * KD);
    {
        __half* As = gsm;
        __half* Bs = gsm + 128 * LDGH;
#pragma unroll
        for (int p = 0; p < 2; p++) {
            float4 va = pa[p];
            uint2 u = make_uint2(packh2(va.x, va.y), packh2(va.z, va.w));
            *(uint2*)&As[(p * 64 + grow) * LDGH + gcol] = u;
        }
#pragma unroll
        for (int p = 0; p < 4; p++) {
            float4 vb = pb[p];
            uint2 u = make_uint2(packh2(vb.x, vb.y), packh2(vb.z, vb.w));
            *(uint2*)&Bs[(p * 64 + grow) * LDGH + gcol] = u;
        }
    }
#pragma unroll
    for (int p = 0; p < 2; p++)
        pa[p] = *(const float4*)(ap + 32 + (size_t)p * 64 * KD);
#pragma unroll
    for (int p = 0; p < 4; p++)
        pb[p] = *(const float4*)(wp + 32 + (size_t)p * 64 * KD);
    __syncthreads();

    for (int kt = 0; kt < ktiles; kt++) {
        const __half* As = gsm + (kt & 1) * GSTAGE_H;
        const __half* Bs = As + 128 * LDGH;

#pragma unroll
        for (int ks = 0; ks < 2; ks++) {
            const int k0 = ks * 16;
            unsigned af[4][4], bf[2][4];
#pragma unroll
            for (int mt = 0; mt < 4; mt++)
                ldmx4(af[mt], &As[(wm + mt * 16 + lmRow) * LDGH + k0 + lmColH]);
#pragma unroll
            for (int ntp = 0; ntp < 2; ntp++)
                ldmx4(bf[ntp], &Bs[(wn + ntp * 16 + lmRow) * LDGH + k0 + lmColH]);
#pragma unroll
            for (int mt = 0; mt < 4; mt++)
#pragma unroll
                for (int nt = 0; nt < 4; nt++)
                    mma16h(acc[mt][nt], af[mt], bf[nt >> 1][nt & 1],
                           bf[nt >> 1][(nt & 1) + 2]);
        }

        if (kt + 1 < ktiles) {
            __half* An = gsm + ((kt + 1) & 1) * GSTAGE_H;
            __half* Bn = An + 128 * LDGH;
#pragma unroll
            for (int p = 0; p < 2; p++) {
                float4 va = pa[p];
                uint2 u = make_uint2(packh2(va.x, va.y), packh2(va.z, va.w));
                *(uint2*)&An[(p * 64 + grow) * LDGH + gcol] = u;
            }
#pragma unroll
            for (int p = 0; p < 4; p++) {
                float4 vb = pb[p];
                uint2 u = make_uint2(packh2(vb.x, vb.y), packh2(vb.z, vb.w));
                *(uint2*)&Bn[(p * 64 + grow) * LDGH + gcol] = u;
            }
        }
        if (kt + 2 < ktiles) {
            const float* an = ap + (kt + 2) * 32;
            const float* wn2 = wp + (kt + 2) * 32;
#pragma unroll
            for (int p = 0; p < 2; p++)
                pa[p] = *(const float4*)(an + (size_t)p * 64 * KD);
#pragma unroll
            for (int p = 0; p < 4; p++)
                pb[p] = *(const float4*)(wn2 + (size_t)p * 64 * KD);
        }
        __syncthreads();
    }

#pragma unroll
    for (int mt = 0; mt < 4; mt++)
#pragma unroll
        for (int nt = 0; nt < 4; nt++) {
            const int row = mBase + wm + mt * 16 + lg;
            const int col = nl0 + wn + nt * 8 + 2 * t4;
            *(__half2*)&C[(size_t)row * cN + col] =
                __floats2half2_rn(acc[mt][nt][0] * oscale, acc[mt][nt][1] * oscale);
            *(__half2*)&C[(size_t)(row + 8) * cN + col] =
                __floats2half2_rn(acc[mt][nt][2] * oscale, acc[mt][nt][3] * oscale);
        }
}

// ---------------------------------------------------------------------------
// fp16 flash attention. Br=128, Bc=64, 8 warps, single-buffered K/V.
// Q fragments in registers; P A-frag == S C-frag (no shuffle);
// V via ldmatrix.trans.
// ---------------------------------------------------------------------------
#define BQ 128
#define BK 64
#define LDQH 136
#define LDKH 136
#define LDVH 136
#define ATTN_SMEM_BYTES (2 * BK * LDKH * 2)   // Ks+Vs (Qstage overlays, same size)

__global__ __launch_bounds__(256, 1) void attn_mma(const __half* __restrict__ q,
                                                   const __half* __restrict__ k,
                                                   const __half* __restrict__ v,
                                                   float* __restrict__ out) {
    extern __shared__ __align__(16) char smRaw[];
    __half* Ks = (__half*)smRaw;            // [BK][LDKH]
    __half* Vs = Ks + BK * LDKH;            // [BK][LDVH]
    __half* Qstage = (__half*)smRaw;        // [BQ][LDQH] overlay (pre-loop)

    const int tid = threadIdx.x;
    const int w = tid >> 5;
    const int lane = tid & 31;
    const int lg = lane >> 2;
    const int t4 = lane & 3;

    const int qt = gridDim.x - 1 - blockIdx.x;   // heavy tiles first
    const int h = blockIdx.y;
    const int b = blockIdx.z;
    const int grp = h / (HEADS / GROUPS);
    const int qBase = qt * BQ;
    const int wq0 = w * 16;

    const int lmRow = lane & 15;
    const int lmColH = (lane >> 4) * 8;

    // ---- stage Q (already scaled fp16) ----
    {
        const int row = tid & 127;
        const int hsel = tid >> 7;
        const __half* qp = q + (size_t)(b * SEQ + qBase + row) * DM + h * HD +
                           hsel * 64;
        __half* qd = Qstage + row * LDQH + hsel * 64;
#pragma unroll
        for (int i = 0; i < 8; i++)
            *(uint4*)(qd + i * 8) = *(const uint4*)(qp + i * 8);
    }
    __syncthreads();

    unsigned qf[8][4];
#pragma unroll
    for (int ks = 0; ks < 8; ks++)
        ldmx4(qf[ks], &Qstage[(wq0 + lmRow) * LDQH + ks * 16 + lmColH]);

    float oacc[16][4];
#pragma unroll
    for (int nt = 0; nt < 16; nt++)
#pragma unroll
        for (int i = 0; i < 4; i++) oacc[nt][i] = 0.f;

    float m0 = -1e30f, m1 = -1e30f, l0 = 0.f, l1 = 0.f;
    const int lastRow = qBase + wq0 + 15;
    const int row0g = qBase + wq0 + lg;
    const int nkt = (qBase + BQ) / BK;

    const int krow = tid & 63;
    const int quarter = tid >> 6;

    for (int kt = 0; kt < nkt; kt++) {
        const int kBase = kt * BK;
        __syncthreads();   // prev iter fragment reads done (also protects Qstage)

        // ---- cooperative K/V tile load (fp16, no conversion) ----
        {
            const size_t base = (size_t)(b * SEQ + kBase + krow) * DKV +
                                grp * HD + quarter * 32;
            const __half* kp = k + base;
            const __half* vp = v + base;
            __half* kd = Ks + krow * LDKH + quarter * 32;
            __half* vd = Vs + krow * LDVH + quarter * 32;
#pragma unroll
            for (int i = 0; i < 4; i++) {
                *(uint4*)(kd + i * 8) = *(const uint4*)(kp + i * 8);
                *(uint4*)(vd + i * 8) = *(const uint4*)(vp + i * 8);
            }
        }
        __syncthreads();

        if (kBase > lastRow) continue;   // warp-uniform; barrier counts match

        // ---- phase A: S = Q K^T ----
        float sacc[8][4];
#pragma unroll
        for (int nt = 0; nt < 8; nt++)
#pragma unroll
            for (int i = 0; i < 4; i++) sacc[nt][i] = 0.f;

#pragma unroll
        for (int ks = 0; ks < 8; ks++) {
            const int k0 = ks * 16;
#pragma unroll
            for (int ntp = 0; ntp < 4; ntp++) {
                unsigned bq[4];
                ldmx4(bq, &Ks[(ntp * 16 + lmRow) * LDKH + k0 + lmColH]);
                mma16h(sacc[2 * ntp], qf[ks], bq[0], bq[2]);
                mma16h(sacc[2 * ntp + 1], qf[ks], bq[1], bq[3]);
            }
        }

        // ---- causal mask ----
        if (kBase + BK - 1 > qBase + wq0) {
#pragma unroll
            for (int nt = 0; nt < 8; nt++) {
                const int c0 = kBase + nt * 8 + 2 * t4;
                if (c0 > row0g) sacc[nt][0] = -1e30f;
                if (c0 + 1 > row0g) sacc[nt][1] = -1e30f;
                if (c0 > row0g + 8) sacc[nt][2] = -1e30f;
                if (c0 + 1 > row0g + 8) sacc[nt][3] = -1e30f;
            }
        }

        // ---- online softmax (base-2), registers + quad shfl ----
        float mx0 = -1e30f, mx1 = -1e30f;
#pragma unroll
        for (int nt = 0; nt < 8; nt++) {
            mx0 = fmaxf(mx0, fmaxf(sacc[nt][0], sacc[nt][1]));
            mx1 = fmaxf(mx1, fmaxf(sacc[nt][2], sacc[nt][3]));
        }
        mx0 = fmaxf(mx0, __shfl_xor_sync(0xffffffff, mx0, 1));
        mx0 = fmaxf(mx0, __shfl_xor_sync(0xffffffff, mx0, 2));
        mx1 = fmaxf(mx1, __shfl_xor_sync(0xffffffff, mx1, 1));
        mx1 = fmaxf(mx1, __shfl_xor_sync(0xffffffff, mx1, 2));

        const float mn0 = fmaxf(m0, mx0);
        const float mn1 = fmaxf(m1, mx1);
        const float sc0 = fexp2(m0 - mn0);
        const float sc1 = fexp2(m1 - mn1);

        float sum0 = 0.f, sum1 = 0.f;
#pragma unroll
        for (int nt = 0; nt < 8; nt++) {
            float p0 = fexp2(sacc[nt][0] - mn0);
            float p1 = fexp2(sacc[nt][1] - mn0);
            float p2 = fexp2(sacc[nt][2] - mn1);
            float p3 = fexp2(sacc[nt][3] - mn1);
            sacc[nt][0] = p0; sacc[nt][1] = p1;
            sacc[nt][2] = p2; sacc[nt][3] = p3;
            sum0 += p0 + p1;
            sum1 += p2 + p3;
        }
        sum0 += __shfl_xor_sync(0xffffffff, sum0, 1);
        sum0 += __shfl_xor_sync(0xffffffff, sum0, 2);
        sum1 += __shfl_xor_sync(0xffffffff, sum1, 1);
        sum1 += __shfl_xor_sync(0xffffffff, sum1, 2);

        l0 = l0 * sc0 + sum0;  m0 = mn0;
        l1 = l1 * sc1 + sum1;  m1 = mn1;

#pragma unroll
        for (int nt = 0; nt < 16; nt++) {
            oacc[nt][0] *= sc0;
            oacc[nt][1] *= sc0;
            oacc[nt][2] *= sc1;
            oacc[nt][3] *= sc1;
        }

        // ---- phase C: O += P V (P A-frag == S C-frag; V via ldmatrix.trans) ----
#pragma unroll
        for (int kt2 = 0; kt2 < 4; kt2++) {
            unsigned pf[4];
            pf[0] = packh2(sacc[2 * kt2][0], sacc[2 * kt2][1]);
            pf[1] = packh2(sacc[2 * kt2][2], sacc[2 * kt2][3]);
            pf[2] = packh2(sacc[2 * kt2 + 1][0], sacc[2 * kt2 + 1][1]);
            pf[3] = packh2(sacc[2 * kt2 + 1][2], sacc[2 * kt2 + 1][3]);
#pragma unroll
            for (int dblk = 0; dblk < 8; dblk++) {
                unsigned bv[4];
                ldmx4t(bv, &Vs[(kt2 * 16 + lmRow) * LDVH + dblk * 16 + lmColH]);
                mma16h(oacc[2 * dblk], pf, bv[0], bv[1]);
                mma16h(oacc[2 * dblk + 1], pf, bv[2], bv[3]);
            }
        }
    }

    // ---- finalize + write (fp32) ----
    const float inv0 = 1.0f / l0;
    const float inv1 = 1.0f / l1;
#pragma unroll
    for (int nt = 0; nt < 16; nt++) {
        const int d = h * HD + nt * 8 + 2 * t4;
        *(float2*)&out[(size_t)(b * SEQ + row0g) * DM + d] =
            make_float2(oacc[nt][0] * inv0, oacc[nt][1] * inv0);
        *(float2*)&out[(size_t)(b * SEQ + row0g + 8) * DM + d] =
            make_float2(oacc[nt][2] * inv1, oacc[nt][3] * inv1);
    }
}

// ---------------------------------------------------------------------------
extern "C" void kernel_launch(void* const* d_in, const int* in_sizes, int n_in,
                              void* d_out, int out_size) {
    const float* x = (const float*)d_in[0];
    const float* Wq = (const float*)d_in[1];
    const float* Wk = (const float*)d_in[2];
    const float* Wv = (const float*)d_in[3];
    float* out = (float*)d_out;

    __half *pq = nullptr, *pk = nullptr, *pv = nullptr;
    cudaGetSymbolAddress((void**)&pq, g_q);
    cudaGetSymbolAddress((void**)&pk, g_k);
    cudaGetSymbolAddress((void**)&pv, g_v);

    cudaFuncSetAttribute(gemm_qkv, cudaFuncAttributeMaxDynamicSharedMemorySize,
                         GEMM_SMEM_BYTES);
    dim3 gthr(512);
    dim3 gg(12, 32);
    gemm_qkv<<<gg, gthr, GEMM_SMEM_BYTES>>>(x, Wq, Wk, Wv);

    cudaFuncSetAttribute(attn_mma, cudaFuncAttributeMaxDynamicSharedMemorySize,
                         ATTN_SMEM_BYTES);
    dim3 athr(256);
    dim3 ga(SEQ / BQ, HEADS, BATCH);
    attn_mma<<<ga, athr, ATTN_SMEM_BYTES>>>(pq, pk, pv, out);
}

// round 9
// speedup vs baseline: 1.7660x; 1.0892x over previous
#include <cuda_runtime.h>
#include <cuda_fp16.h>
#include <math.h>

#define HEADS 16
#define GROUPS 4
#define BATCH 2
#define SEQ 2048
#define DM 2048
#define DKV 512
#define HD 128
#define KD 2048

// Scratch (allocation-free rule: __device__ globals)
__device__ __half g_q[BATCH * SEQ * DM];
__device__ __half g_k[BATCH * SEQ * DKV];
__device__ __half g_v[BATCH * SEQ * DKV];
__device__ __half g_xh[BATCH * SEQ * DM];
__device__ __half g_wqh[DM * KD];
__device__ __half g_wkh[DKV * KD];
__device__ __half g_wvh[DKV * KD];

// ---------------------------------------------------------------------------
// helpers
// ---------------------------------------------------------------------------
__device__ __forceinline__ float fexp2(float x) {
    float r;
    asm("ex2.approx.f32 %0, %1;" : "=f"(r) : "f"(x));
    return r;
}

__device__ __forceinline__ unsigned packh2(float lo, float hi) {
    __half2 h = __floats2half2_rn(lo, hi);
    return *reinterpret_cast<unsigned*>(&h);
}

__device__ __forceinline__ void mma16h(float c[4], const unsigned a[4],
                                       unsigned b0, unsigned b1) {
    asm volatile(
        "mma.sync.aligned.m16n8k16.row.col.f32.f16.f16.f32 "
        "{%0,%1,%2,%3}, {%4,%5,%6,%7}, {%8,%9}, {%0,%1,%2,%3};\n"
        : "+f"(c[0]), "+f"(c[1]), "+f"(c[2]), "+f"(c[3])
        : "r"(a[0]), "r"(a[1]), "r"(a[2]), "r"(a[3]), "r"(b0), "r"(b1));
}

__device__ __forceinline__ void ldmx4(unsigned r[4], const __half* p) {
    unsigned addr = (unsigned)__cvta_generic_to_shared(p);
    asm volatile(
        "ldmatrix.sync.aligned.m8n8.x4.shared.b16 {%0,%1,%2,%3}, [%4];"
        : "=r"(r[0]), "=r"(r[1]), "=r"(r[2]), "=r"(r[3])
        : "r"(addr));
}

__device__ __forceinline__ void ldmx4t(unsigned r[4], const __half* p) {
    unsigned addr = (unsigned)__cvta_generic_to_shared(p);
    asm volatile(
        "ldmatrix.sync.aligned.m8n8.x4.trans.shared.b16 {%0,%1,%2,%3}, [%4];"
        : "=r"(r[0]), "=r"(r[1]), "=r"(r[2]), "=r"(r[3])
        : "r"(addr));
}

__device__ __forceinline__ void cpa16(__half* dst, const __half* src) {
    unsigned d = (unsigned)__cvta_generic_to_shared(dst);
    asm volatile("cp.async.cg.shared.global [%0], [%1], 16;" :: "r"(d), "l"(src));
}
#define CP_COMMIT() asm volatile("cp.async.commit_group;" ::: "memory")
#define CP_WAIT1() asm volatile("cp.async.wait_group 1;" ::: "memory")

// ---------------------------------------------------------------------------
// fp32 -> fp16 conversion (elementwise, float4 granularity)
// ---------------------------------------------------------------------------
__global__ __launch_bounds__(256) void cvt2h(const float* __restrict__ src,
                                             __half* __restrict__ dst, int n4) {
    int i = blockIdx.x * blockDim.x + threadIdx.x;
    if (i < n4) {
        float4 v = *(const float4*)(src + i * 4);
        *(uint2*)(dst + i * 4) = make_uint2(packh2(v.x, v.y), packh2(v.z, v.w));
    }
}

// ---------------------------------------------------------------------------
// Fused QKV GEMM, fp16 inputs via cp.async 3-stage pipeline, 512 threads.
// CTA tile 128x256x32, warp tile 64x32. Epilogue stores fp16 (Q pre-scaled).
// ---------------------------------------------------------------------------
#define LDGH 40
#define GSTG_H (128 * LDGH + 256 * LDGH)     // halfs per stage
#define GEMM_SMEM_BYTES (3 * GSTG_H * 2)     // 92160

__global__ __launch_bounds__(512, 1) void gemm_qkv(const __half* __restrict__ xh) {
    extern __shared__ __align__(16) char gsmRaw[];
    __half* gsm = (__half*)gsmRaw;

    const int tid = threadIdx.x;
    const int w = tid >> 5;
    const int lane = tid & 31;
    const int lg = lane >> 2;
    const int t4 = lane & 3;
    const int wm = (w & 1) * 64;
    const int wn = (w >> 1) * 32;
    const int mBase = blockIdx.y * 128;
    const int nb = blockIdx.x;

    const float qscale = 0.08838834764831845f * 1.4426950408889634f;

    const __half* W;
    __half* C;
    int cN, nl0;
    float oscale;
    if (nb < 8)       { W = g_wqh; C = g_q; cN = DM;  nl0 = nb * 256;        oscale = qscale; }
    else if (nb < 10) { W = g_wkh; C = g_k; cN = DKV; nl0 = (nb - 8) * 256;  oscale = 1.f; }
    else              { W = g_wvh; C = g_v; cN = DKV; nl0 = (nb - 10) * 256; oscale = 1.f; }

    float acc[4][4][4];
#pragma unroll
    for (int mt = 0; mt < 4; mt++)
#pragma unroll
        for (int nt = 0; nt < 4; nt++)
#pragma unroll
            for (int i = 0; i < 4; i++) acc[mt][nt][i] = 0.f;

    // cp.async mapping: row = tid>>2 (0..127), chunk col = (tid&3)*8
    const int arow = tid >> 2;
    const int ac8 = (tid & 3) * 8;
    const __half* apc = xh + (size_t)(mBase + arow) * KD + ac8;
    const __half* wpc0 = W + (size_t)(nl0 + arow) * KD + ac8;
    const __half* wpc1 = W + (size_t)(nl0 + 128 + arow) * KD + ac8;

    const int lmRow = lane & 15;
    const int lmColH = (lane >> 4) * 8;
    const int ktiles = KD / 32;

    // prologue: tiles 0,1 -> stages 0,1
#pragma unroll
    for (int t = 0; t < 2; t++) {
        __half* As = gsm + t * GSTG_H;
        __half* Bs = As + 128 * LDGH;
        cpa16(&As[arow * LDGH + ac8], apc + t * 32);
        cpa16(&Bs[arow * LDGH + ac8], wpc0 + t * 32);
        cpa16(&Bs[(128 + arow) * LDGH + ac8], wpc1 + t * 32);
        CP_COMMIT();
    }

    for (int kt = 0; kt < ktiles; kt++) {
        CP_WAIT1();
        __syncthreads();

        if (kt + 2 < ktiles) {
            __half* As = gsm + ((kt + 2) % 3) * GSTG_H;
            __half* Bs = As + 128 * LDGH;
            const int off = (kt + 2) * 32;
            cpa16(&As[arow * LDGH + ac8], apc + off);
            cpa16(&Bs[arow * LDGH + ac8], wpc0 + off);
            cpa16(&Bs[(128 + arow) * LDGH + ac8], wpc1 + off);
        }
        CP_COMMIT();

        const __half* As = gsm + (kt % 3) * GSTG_H;
        const __half* Bs = As + 128 * LDGH;
#pragma unroll
        for (int ks = 0; ks < 2; ks++) {
            const int k0 = ks * 16;
            unsigned af[4][4], bf[2][4];
#pragma unroll
            for (int mt = 0; mt < 4; mt++)
                ldmx4(af[mt], &As[(wm + mt * 16 + lmRow) * LDGH + k0 + lmColH]);
#pragma unroll
            for (int ntp = 0; ntp < 2; ntp++)
                ldmx4(bf[ntp], &Bs[(wn + ntp * 16 + lmRow) * LDGH + k0 + lmColH]);
#pragma unroll
            for (int mt = 0; mt < 4; mt++)
#pragma unroll
                for (int nt = 0; nt < 4; nt++)
                    mma16h(acc[mt][nt], af[mt], bf[nt >> 1][nt & 1],
                           bf[nt >> 1][(nt & 1) + 2]);
        }
    }

#pragma unroll
    for (int mt = 0; mt < 4; mt++)
#pragma unroll
        for (int nt = 0; nt < 4; nt++) {
            const int row = mBase + wm + mt * 16 + lg;
            const int col = nl0 + wn + nt * 8 + 2 * t4;
            *(__half2*)&C[(size_t)row * cN + col] =
                __floats2half2_rn(acc[mt][nt][0] * oscale, acc[mt][nt][1] * oscale);
            *(__half2*)&C[(size_t)(row + 8) * cN + col] =
                __floats2half2_rn(acc[mt][nt][2] * oscale, acc[mt][nt][3] * oscale);
        }
}

// ---------------------------------------------------------------------------
// fp16 flash attention, cp.async 3-stage K/V pipeline, 1 barrier/iter.
// Br=128, Bc=64, 8 warps. Q fragments in registers; P A-frag == S C-frag.
// ---------------------------------------------------------------------------
#define BQ 128
#define BK 64
#define LDQH 136
#define LDKH 136
#define LDVH 136
#define ASTG_H (2 * BK * LDKH)               // K+V halfs per stage = 17408
#define ATTN_SMEM_BYTES (3 * ASTG_H * 2)     // 104448

__global__ __launch_bounds__(256, 1) void attn_mma(const __half* __restrict__ q,
                                                   const __half* __restrict__ k,
                                                   const __half* __restrict__ v,
                                                   float* __restrict__ out) {
    extern __shared__ __align__(16) char smRaw[];
    __half* stg = (__half*)smRaw;          // 3 stages: [Ks|Vs] each
    __half* Qstage = (__half*)smRaw;       // overlay (pre-loop only)

    const int tid = threadIdx.x;
    const int w = tid >> 5;
    const int lane = tid & 31;
    const int lg = lane >> 2;
    const int t4 = lane & 3;

    const int qt = gridDim.x - 1 - blockIdx.x;   // heavy tiles first
    const int h = blockIdx.y;
    const int b = blockIdx.z;
    const int grp = h / (HEADS / GROUPS);
    const int qBase = qt * BQ;
    const int wq0 = w * 16;

    const int lmRow = lane & 15;
    const int lmColH = (lane >> 4) * 8;

    // ---- stage Q (pre-scaled fp16) and pull fragments ----
    {
        const int row = tid & 127;
        const int hsel = tid >> 7;
        const __half* qp = q + (size_t)(b * SEQ + qBase + row) * DM + h * HD +
                           hsel * 64;
        __half* qd = Qstage + row * LDQH + hsel * 64;
#pragma unroll
        for (int i = 0; i < 8; i++)
            *(uint4*)(qd + i * 8) = *(const uint4*)(qp + i * 8);
    }
    __syncthreads();

    unsigned qf[8][4];
#pragma unroll
    for (int ks = 0; ks < 8; ks++)
        ldmx4(qf[ks], &Qstage[(wq0 + lmRow) * LDQH + ks * 16 + lmColH]);
    __syncthreads();   // qf pulled before cp.async overwrites Qstage

    const int nkt = (qBase + BQ) / BK;   // >= 2
    const int krow = tid & 63;
    const int quarter = tid >> 6;
    const size_t kvcol = grp * HD + quarter * 32;

    // prologue: tiles 0,1 -> stages 0,1
#pragma unroll
    for (int t = 0; t < 2; t++) {
        __half* Ks = stg + t * ASTG_H;
        __half* Vs = Ks + BK * LDKH;
        const size_t base = (size_t)(b * SEQ + t * BK + krow) * DKV + kvcol;
        __half* kd = Ks + krow * LDKH + quarter * 32;
        __half* vd = Vs + krow * LDVH + quarter * 32;
#pragma unroll
        for (int i = 0; i < 4; i++) {
            cpa16(kd + i * 8, k + base + i * 8);
            cpa16(vd + i * 8, v + base + i * 8);
        }
        CP_COMMIT();
    }

    float oacc[16][4];
#pragma unroll
    for (int nt = 0; nt < 16; nt++)
#pragma unroll
        for (int i = 0; i < 4; i++) oacc[nt][i] = 0.f;

    float m0 = -1e30f, m1 = -1e30f, l0 = 0.f, l1 = 0.f;
    const int lastRow = qBase + wq0 + 15;
    const int row0g = qBase + wq0 + lg;

    for (int kt = 0; kt < nkt; kt++) {
        const int kBase = kt * BK;
        CP_WAIT1();
        __syncthreads();

        // issue tile kt+2 into the stage freed at iter kt-1
        if (kt + 2 < nkt) {
            __half* Ks = stg + ((kt + 2) % 3) * ASTG_H;
            __half* Vs = Ks + BK * LDKH;
            const size_t base = (size_t)(b * SEQ + (kt + 2) * BK + krow) * DKV +
                                kvcol;
            __half* kd = Ks + krow * LDKH + quarter * 32;
            __half* vd = Vs + krow * LDVH + quarter * 32;
#pragma unroll
            for (int i = 0; i < 4; i++) {
                cpa16(kd + i * 8, k + base + i * 8);
                cpa16(vd + i * 8, v + base + i * 8);
            }
        }
        CP_COMMIT();

        if (kBase > lastRow) continue;   // warp-uniform

        const __half* Ks = stg + (kt % 3) * ASTG_H;
        const __half* Vs = Ks + BK * LDKH;

        // ---- phase A: S = Q K^T ----
        float sacc[8][4];
#pragma unroll
        for (int nt = 0; nt < 8; nt++)
#pragma unroll
            for (int i = 0; i < 4; i++) sacc[nt][i] = 0.f;

#pragma unroll
        for (int ks = 0; ks < 8; ks++) {
            const int k0 = ks * 16;
#pragma unroll
            for (int ntp = 0; ntp < 4; ntp++) {
                unsigned bq[4];
                ldmx4(bq, &Ks[(ntp * 16 + lmRow) * LDKH + k0 + lmColH]);
                mma16h(sacc[2 * ntp], qf[ks], bq[0], bq[2]);
                mma16h(sacc[2 * ntp + 1], qf[ks], bq[1], bq[3]);
            }
        }

        // ---- causal mask ----
        if (kBase + BK - 1 > qBase + wq0) {
#pragma unroll
            for (int nt = 0; nt < 8; nt++) {
                const int c0 = kBase + nt * 8 + 2 * t4;
                if (c0 > row0g) sacc[nt][0] = -1e30f;
                if (c0 + 1 > row0g) sacc[nt][1] = -1e30f;
                if (c0 > row0g + 8) sacc[nt][2] = -1e30f;
                if (c0 + 1 > row0g + 8) sacc[nt][3] = -1e30f;
            }
        }

        // ---- online softmax (base-2), registers + quad shfl ----
        float mx0 = -1e30f, mx1 = -1e30f;
#pragma unroll
        for (int nt = 0; nt < 8; nt++) {
            mx0 = fmaxf(mx0, fmaxf(sacc[nt][0], sacc[nt][1]));
            mx1 = fmaxf(mx1, fmaxf(sacc[nt][2], sacc[nt][3]));
        }
        mx0 = fmaxf(mx0, __shfl_xor_sync(0xffffffff, mx0, 1));
        mx0 = fmaxf(mx0, __shfl_xor_sync(0xffffffff, mx0, 2));
        mx1 = fmaxf(mx1, __shfl_xor_sync(0xffffffff, mx1, 1));
        mx1 = fmaxf(mx1, __shfl_xor_sync(0xffffffff, mx1, 2));

        const float mn0 = fmaxf(m0, mx0);
        const float mn1 = fmaxf(m1, mx1);
        const float sc0 = fexp2(m0 - mn0);
        const float sc1 = fexp2(m1 - mn1);

        float sum0 = 0.f, sum1 = 0.f;
#pragma unroll
        for (int nt = 0; nt < 8; nt++) {
            float p0 = fexp2(sacc[nt][0] - mn0);
            float p1 = fexp2(sacc[nt][1] - mn0);
            float p2 = fexp2(sacc[nt][2] - mn1);
            float p3 = fexp2(sacc[nt][3] - mn1);
            sacc[nt][0] = p0; sacc[nt][1] = p1;
            sacc[nt][2] = p2; sacc[nt][3] = p3;
            sum0 += p0 + p1;
            sum1 += p2 + p3;
        }
        sum0 += __shfl_xor_sync(0xffffffff, sum0, 1);
        sum0 += __shfl_xor_sync(0xffffffff, sum0, 2);
        sum1 += __shfl_xor_sync(0xffffffff, sum1, 1);
        sum1 += __shfl_xor_sync(0xffffffff, sum1, 2);

        l0 = l0 * sc0 + sum0;  m0 = mn0;
        l1 = l1 * sc1 + sum1;  m1 = mn1;

#pragma unroll
        for (int nt = 0; nt < 16; nt++) {
            oacc[nt][0] *= sc0;
            oacc[nt][1] *= sc0;
            oacc[nt][2] *= sc1;
            oacc[nt][3] *= sc1;
        }

        // ---- phase C: O += P V ----
#pragma unroll
        for (int kt2 = 0; kt2 < 4; kt2++) {
            unsigned pf[4];
            pf[0] = packh2(sacc[2 * kt2][0], sacc[2 * kt2][1]);
            pf[1] = packh2(sacc[2 * kt2][2], sacc[2 * kt2][3]);
            pf[2] = packh2(sacc[2 * kt2 + 1][0], sacc[2 * kt2 + 1][1]);
            pf[3] = packh2(sacc[2 * kt2 + 1][2], sacc[2 * kt2 + 1][3]);
#pragma unroll
            for (int dblk = 0; dblk < 8; dblk++) {
                unsigned bv[4];
                ldmx4t(bv, &Vs[(kt2 * 16 + lmRow) * LDVH + dblk * 16 + lmColH]);
                mma16h(oacc[2 * dblk], pf, bv[0], bv[1]);
                mma16h(oacc[2 * dblk + 1], pf, bv[2], bv[3]);
            }
        }
    }

    // ---- finalize + write (fp32) ----
    const float inv0 = 1.0f / l0;
    const float inv1 = 1.0f / l1;
#pragma unroll
    for (int nt = 0; nt < 16; nt++) {
        const int d = h * HD + nt * 8 + 2 * t4;
        *(float2*)&out[(size_t)(b * SEQ + row0g) * DM + d] =
            make_float2(oacc[nt][0] * inv0, oacc[nt][1] * inv0);
        *(float2*)&out[(size_t)(b * SEQ + row0g + 8) * DM + d] =
            make_float2(oacc[nt][2] * inv1, oacc[nt][3] * inv1);
    }
}

// ---------------------------------------------------------------------------
extern "C" void kernel_launch(void* const* d_in, const int* in_sizes, int n_in,
                              void* d_out, int out_size) {
    const float* x = (const float*)d_in[0];
    const float* Wq = (const float*)d_in[1];
    const float* Wk = (const float*)d_in[2];
    const float* Wv = (const float*)d_in[3];
    float* out = (float*)d_out;

    __half *pq, *pk, *pv, *pxh, *pwq, *pwk, *pwv;
    cudaGetSymbolAddress((void**)&pq, g_q);
    cudaGetSymbolAddress((void**)&pk, g_k);
    cudaGetSymbolAddress((void**)&pv, g_v);
    cudaGetSymbolAddress((void**)&pxh, g_xh);
    cudaGetSymbolAddress((void**)&pwq, g_wqh);
    cudaGetSymbolAddress((void**)&pwk, g_wkh);
    cudaGetSymbolAddress((void**)&pwv, g_wvh);

    // fp32 -> fp16 conversions
    cvt2h<<<(BATCH * SEQ * DM / 4 + 255) / 256, 256>>>(x, pxh, BATCH * SEQ * DM / 4);
    cvt2h<<<(DM * KD / 4 + 255) / 256, 256>>>(Wq, pwq, DM * KD / 4);
    cvt2h<<<(DKV * KD / 4 + 255) / 256, 256>>>(Wk, pwk, DKV * KD / 4);
    cvt2h<<<(DKV * KD / 4 + 255) / 256, 256>>>(Wv, pwv, DKV * KD / 4);

    cudaFuncSetAttribute(gemm_qkv, cudaFuncAttributeMaxDynamicSharedMemorySize,
                         GEMM_SMEM_BYTES);
    dim3 gthr(512);
    dim3 gg(12, 32);
    gemm_qkv<<<gg, gthr, GEMM_SMEM_BYTES>>>(pxh);

    cudaFuncSetAttribute(attn_mma, cudaFuncAttributeMaxDynamicSharedMemorySize,
                         ATTN_SMEM_BYTES);
    dim3 athr(256);
    dim3 ga(SEQ / BQ, HEADS, BATCH);
    attn_mma<<<ga, athr, ATTN_SMEM_BYTES>>>(pq, pk, pv, out);
}